// round 11
// baseline (speedup 1.0000x reference)
#include <cuda_runtime.h>
#include <cuda_bf16.h>
#include <cstdint>

#define Bn 2
#define CSn 128
#define CDn 128
#define SDn 8
#define SHn 16
#define SWn 16
#define DDn 16
#define DHn 32
#define DWn 32
#define Pn  (DDn*DHn*DWn)      /* 16384 */
#define Gn 8
#define K3n 27
#define CGn 16                 /* CS/G */
#define NOFF (K3n*3*Gn)        /* 648 */
#define NTAP (Gn*K3n)          /* 216 */
#define WROW 80                /* padded row bytes of A/B smem tiles */
#define WTILE (128*WROW)       /* 10240 B per weight tile */
#define STILE (64*WROW)        /* 5120 B per sample tile */
#define MTILES 6               /* ceil(648/128) m-tiles for offset GEMM */
#define DCN_SMEM (4*WTILE + 4*STILE)   /* 61440 B */

typedef unsigned long long ull;

// ---------------- f32x2 / bf16 helpers ---------------------------------------
__device__ __forceinline__ ull ffma2(ull a, ull b, ull c) {
    ull d;
    asm("fma.rn.f32x2 %0, %1, %2, %3;" : "=l"(d) : "l"(a), "l"(b), "l"(c));
    return d;
}
__device__ __forceinline__ ull dup2(float s) {
    ull d;
    unsigned u = __float_as_uint(s);
    asm("mov.b64 %0, {%1, %1};" : "=l"(d) : "r"(u));
    return d;
}
__device__ __forceinline__ float lo32(ull v) {
    return __uint_as_float((unsigned)(v & 0xffffffffull));
}
__device__ __forceinline__ float hi32(ull v) {
    return __uint_as_float((unsigned)(v >> 32));
}
__device__ __forceinline__ uint32_t cvtbf2(float hi, float lo) { // {hi,lo} packed
    uint32_t r;
    asm("cvt.rn.bf16x2.f32 %0, %1, %2;" : "=r"(r) : "f"(hi), "f"(lo));
    return r;
}

// ---------------- tensor-core helpers ---------------------------------------
__device__ __forceinline__ void ldsm4(uint32_t* r, uint32_t addr) {
    asm volatile("ldmatrix.sync.aligned.m8n8.x4.shared.b16 {%0,%1,%2,%3},[%4];"
        : "=r"(r[0]), "=r"(r[1]), "=r"(r[2]), "=r"(r[3]) : "r"(addr));
}
__device__ __forceinline__ void mma16816(float* d, const uint32_t* a,
                                         uint32_t b0, uint32_t b1) {
    asm volatile(
        "mma.sync.aligned.m16n8k16.row.col.f32.bf16.bf16.f32 "
        "{%0,%1,%2,%3},{%4,%5,%6,%7},{%8,%9},{%0,%1,%2,%3};"
        : "+f"(d[0]), "+f"(d[1]), "+f"(d[2]), "+f"(d[3])
        : "r"(a[0]), "r"(a[1]), "r"(a[2]), "r"(a[3]), "r"(b0), "r"(b1));
}
__device__ __forceinline__ uint32_t packbf(__nv_bfloat16 a, __nv_bfloat16 b) {
    __nv_bfloat162 t = __halves2bfloat162(a, b);
    return *(uint32_t*)&t;
}

// -------- device scratch ----------------------------------------------------
__device__ float g_src_cl[Bn*SDn*SHn*SWn*CSn];   // [b][z][y][x][c]
__device__ float g_up_cl[Bn*Pn*CSn];             // [b][p][c]
__device__ float g_off[Bn*NOFF*Pn];              // [b][o][p]
__device__ __align__(16) uint8_t g_wsplit[(size_t)NTAP*WTILE];       // dcn W hi/lo
__device__ __align__(16) uint8_t g_wosplit[(size_t)MTILES*16*WTILE]; // offset W hi/lo
__device__ __align__(16) __nv_bfloat16 g_cath[(size_t)Bn*Pn*256];    // cat hi [b][p][c]
__device__ __align__(16) __nv_bfloat16 g_catl[(size_t)Bn*Pn*256];    // cat lo

// -------- prep: transposes + bf16 weight splits ------------------------------
__global__ void k_prep(const float* __restrict__ src,
                       const float* __restrict__ woff,
                       const float* __restrict__ wdcn) {
    int i = blockIdx.x * blockDim.x + threadIdx.x;
    const int N1 = Bn*SDn*SHn*SWn*CSn;    // 524288
    const int N3 = NTAP*128*CGn;          // 442368
    const int N4 = MTILES*128*256;        // 196608 (768 o x 256 c)
    if (i < N1) {
        int c = i % CSn;
        int s = (i / CSn) % (SDn*SHn*SWn);
        int b = i / (CSn*SDn*SHn*SWn);
        g_src_cl[i] = src[(b*CSn + c)*(SDn*SHn*SWn) + s];
    } else if (i < N1 + N3) {
        int j = i - N1;
        int cg = j % CGn;
        int o  = (j / CGn) % 128;
        int kk = j / (CGn*128);
        int g = kk / K3n, k = kk % K3n;
        float wv = wdcn[((o*CSn) + g*CGn + cg)*K3n + k];
        __nv_bfloat16 hb = __float2bfloat16(wv);
        __nv_bfloat16 lb = __float2bfloat16(wv - __bfloat162float(hb));
        uint8_t* row = g_wsplit + (size_t)kk*WTILE + o*WROW;
        *(__nv_bfloat16*)(row + cg*2)      = hb;
        *(__nv_bfloat16*)(row + 32 + cg*2) = lb;
    } else if (i < N1 + N3 + N4) {
        int j = i - N1 - N3;
        int c = j % 256;
        int o = j / 256;                  // 0..767 (padded)
        float wv = (o < NOFF) ? woff[o*256 + c] : 0.f;
        __nv_bfloat16 hb = __float2bfloat16(wv);
        __nv_bfloat16 lb = __float2bfloat16(wv - __bfloat162float(hb));
        int mt = o >> 7, kc = c >> 4;
        uint8_t* row = g_wosplit + (size_t)(mt*16 + kc)*WTILE + (o & 127)*WROW;
        *(__nv_bfloat16*)(row + (c & 15)*2)      = hb;
        *(__nv_bfloat16*)(row + 32 + (c & 15)*2) = lb;
    }
}

// -------- trilinear 2x upsample ----------------------------------------------
__global__ void k_upsample() {
    int bp = blockIdx.x;                 // Bn*Pn blocks
    int b = bp / Pn;
    int p = bp % Pn;
    int d = p >> 10, h = (p >> 5) & 31, w = p & 31;

    float zc = d*0.5f - 0.25f, yc = h*0.5f - 0.25f, xc = w*0.5f - 0.25f;
    int zf = (int)floorf(zc), yf = (int)floorf(yc), xf = (int)floorf(xc);
    float fz = zc - zf, fy = yc - yf, fx = xc - xf;
    int z0 = min(max(zf,     0), SDn-1), z1 = min(max(zf + 1, 0), SDn-1);
    int y0 = min(max(yf,     0), SHn-1), y1 = min(max(yf + 1, 0), SHn-1);
    int x0 = min(max(xf,     0), SWn-1), x1 = min(max(xf + 1, 0), SWn-1);

    const float* base = g_src_cl + (size_t)b * (SDn*SHn*SWn) * CSn;
    int c = threadIdx.x;  // 128

    float v000 = base[(z0*256 + y0*16 + x0)*CSn + c];
    float v001 = base[(z0*256 + y0*16 + x1)*CSn + c];
    float v010 = base[(z0*256 + y1*16 + x0)*CSn + c];
    float v011 = base[(z0*256 + y1*16 + x1)*CSn + c];
    float v100 = base[(z1*256 + y0*16 + x0)*CSn + c];
    float v101 = base[(z1*256 + y0*16 + x1)*CSn + c];
    float v110 = base[(z1*256 + y1*16 + x0)*CSn + c];
    float v111 = base[(z1*256 + y1*16 + x1)*CSn + c];

    float r0 = (1.f-fy)*((1.f-fx)*v000 + fx*v001) + fy*((1.f-fx)*v010 + fx*v011);
    float r1 = (1.f-fy)*((1.f-fx)*v100 + fx*v101) + fy*((1.f-fx)*v110 + fx*v111);
    g_up_cl[((size_t)b*Pn + p)*CSn + c] = (1.f-fz)*r0 + fz*r1;
}

// -------- build pre-split bf16 cat image [b][p][256c] ------------------------
__global__ void __launch_bounds__(256) k_cat(const float* __restrict__ dst) {
    __shared__ float cat_s[256*33];
    int blk = blockIdx.x;               // Bn*(Pn/32)
    int b  = blk / (Pn/32);
    int p0 = (blk % (Pn/32)) * 32;
    int t = threadIdx.x;

    for (int i = t; i < 128*32; i += 256) {
        int c = i >> 5, v = i & 31;
        cat_s[c*33 + v] = dst[((size_t)b*CDn + c)*Pn + p0 + v];
    }
    for (int i = t; i < 32*128; i += 256) {
        int v = i >> 7, c = i & 127;
        cat_s[(128 + c)*33 + v] = 2.0f * g_up_cl[((size_t)b*Pn + p0 + v)*CSn + c];
    }
    __syncthreads();

    int v = t & 31, cg = t >> 5;        // 8 groups of 32 channels
    uint32_t oh[16], ol[16];
    #pragma unroll
    for (int j = 0; j < 16; ++j) {
        float f0 = cat_s[(cg*32 + 2*j    )*33 + v];
        float f1 = cat_s[(cg*32 + 2*j + 1)*33 + v];
        uint32_t h = cvtbf2(f1, f0);
        float h0f = __uint_as_float(h << 16);
        float h1f = __uint_as_float(h & 0xffff0000u);
        oh[j] = h;
        ol[j] = cvtbf2(f1 - h1f, f0 - h0f);
    }
    size_t base = ((size_t)b*Pn + p0 + v)*256 + cg*32;
    uint4* dh = (uint4*)&g_cath[base];
    uint4* dl = (uint4*)&g_catl[base];
    #pragma unroll
    for (int j = 0; j < 4; ++j) {
        dh[j] = make_uint4(oh[4*j], oh[4*j+1], oh[4*j+2], oh[4*j+3]);
        dl[j] = make_uint4(ol[4*j], ol[4*j+1], ol[4*j+2], ol[4*j+3]);
    }
}

// -------- offset GEMM on tensor cores, dual N-tile ---------------------------
// block: 128 o x 128 p (2 sub-tiles of 64), 256 threads; W/A shared across tiles.
__global__ void __launch_bounds__(256) k_offmma() {
    __shared__ __align__(16) uint8_t sW[2][WTILE];      // 20KB
    __shared__ __align__(16) uint8_t sS[2][2][STILE];   // 20KB

    int blk = blockIdx.x;               // Bn*MTILES*128 = 1536
    int b  = blk / (MTILES*128);
    int r  = blk % (MTILES*128);
    int mt = r / 128;
    int p0 = (r % 128) * 128;
    int t  = threadIdx.x;
    int w  = t >> 5, l = t & 31;

    float dacc[2][8][4];
    #pragma unroll
    for (int tl = 0; tl < 2; ++tl)
        #pragma unroll
        for (int n = 0; n < 8; ++n)
            #pragma unroll
            for (int j = 0; j < 4; ++j) dacc[tl][n][j] = 0.f;

    int btile = t >> 7, brow = (t & 127) >> 1, bpart = t & 1;
    const __nv_bfloat16* catsrc = (bpart ? g_catl : g_cath)
                                + ((size_t)b*Pn + p0 + btile*64 + brow)*256;

    auto domma = [&](int buf) {
        uint32_t sWb = (uint32_t)__cvta_generic_to_shared(&sW[buf][0]);
        uint32_t aaddr = sWb + (w*16 + (l & 15))*WROW + (l >> 4)*16;
        uint32_t ah[4], al[4];
        ldsm4(ah, aaddr);
        ldsm4(al, aaddr + 32);
        uint32_t br = 8*(l >> 4) + (l & 7);
        uint32_t bc = ((l >> 3) & 1)*16;
        #pragma unroll
        for (int tl = 0; tl < 2; ++tl) {
            uint32_t sSb = (uint32_t)__cvta_generic_to_shared(&sS[buf][tl][0]);
            #pragma unroll
            for (int nc = 0; nc < 4; ++nc) {
                uint32_t baddr = sSb + (nc*16 + br)*WROW + bc;
                uint32_t bh[4], bl[4];
                ldsm4(bh, baddr);
                ldsm4(bl, baddr + 32);
                mma16816(dacc[tl][2*nc  ], ah, bh[0], bh[1]);
                mma16816(dacc[tl][2*nc  ], ah, bl[0], bl[1]);
                mma16816(dacc[tl][2*nc  ], al, bh[0], bh[1]);
                mma16816(dacc[tl][2*nc+1], ah, bh[2], bh[3]);
                mma16816(dacc[tl][2*nc+1], ah, bl[2], bl[3]);
                mma16816(dacc[tl][2*nc+1], al, bh[2], bh[3]);
            }
        }
    };

    // prologue: chunk 0
    {
        const uint4* srcW = (const uint4*)(g_wosplit + (size_t)(mt*16)*WTILE);
        uint4* dW = (uint4*)sW[0];
        dW[t] = srcW[t];
        dW[t + 256] = srcW[t + 256];
        if (t < 128) dW[t + 512] = srcW[t + 512];
        const uint4* s = (const uint4*)catsrc;
        uint4* dr = (uint4*)(sS[0][btile] + brow*WROW + bpart*32);
        dr[0] = s[0]; dr[1] = s[1];
    }
    __syncthreads();

    for (int kc = 0; kc < 16; ++kc) {
        int cur = kc & 1;
        bool more = (kc + 1 < 16);
        uint4 wa, wb, wc2, b0, b1;
        if (more) {
            const uint4* srcW = (const uint4*)(g_wosplit + (size_t)(mt*16 + kc + 1)*WTILE);
            wa = srcW[t];
            wb = srcW[t + 256];
            if (t < 128) wc2 = srcW[t + 512];
            const uint4* s = (const uint4*)(catsrc + (kc + 1)*16);
            b0 = s[0]; b1 = s[1];
        }
        domma(cur);
        if (more) {
            int nb = cur ^ 1;
            uint4* dW = (uint4*)sW[nb];
            dW[t] = wa;
            dW[t + 256] = wb;
            if (t < 128) dW[t + 512] = wc2;
            uint4* dr = (uint4*)(sS[nb][btile] + brow*WROW + bpart*32);
            dr[0] = b0; dr[1] = b1;
        }
        __syncthreads();
    }

    // epilogue: write g_off (fp32, guarded o<648), both sub-tiles
    int g = l >> 2, tq = l & 3;
    int o0 = mt*128 + w*16 + g;
    int o1 = o0 + 8;
    #pragma unroll
    for (int tl = 0; tl < 2; ++tl) {
        size_t base0 = ((size_t)b*NOFF + o0)*Pn + p0 + tl*64 + 2*tq;
        size_t base1 = base0 + (size_t)8*Pn - (size_t)(o0)*Pn + (size_t)o1*Pn;
        base1 = ((size_t)b*NOFF + o1)*Pn + p0 + tl*64 + 2*tq;
        #pragma unroll
        for (int n = 0; n < 8; ++n) {
            if (o0 < NOFF)
                *(float2*)&g_off[base0 + n*8] = make_float2(dacc[tl][n][0], dacc[tl][n][1]);
            if (o1 < NOFF)
                *(float2*)&g_off[base1 + n*8] = make_float2(dacc[tl][n][2], dacc[tl][n][3]);
        }
    }
}

// -------- fused deformable sampling + bf16-split tensor GEMM + ReLU ---------
// block: 64 voxels, 256 threads, 2 CTAs/SM; 4-buffer ring, 2 taps per barrier.
// gather: thread-half (t>>7) picks which pipelined tap to gather; q = t&1
// selects 8 channels. Coordinate math 2x/voxel (was 4x).
__global__ void __launch_bounds__(256, 2) k_dcn(float* __restrict__ out) {
    extern __shared__ __align__(16) uint8_t dyn[];
    uint8_t* sW = dyn;                  // 4 x WTILE
    uint8_t* sS = dyn + 4*WTILE;        // 4 x STILE

    int blk = blockIdx.x;               // Bn*(Pn/64) = 512
    int b  = blk >> 8;
    int p0 = (blk & 255) * 64;
    int t  = threadIdx.x;
    int w  = t >> 5, l = t & 31;
    int vv = (t >> 1) & 63, q = t & 1, tapsel = t >> 7;

    float dacc[8][4];
    #pragma unroll
    for (int n = 0; n < 8; ++n)
        #pragma unroll
        for (int j = 0; j < 4; ++j) dacc[n][j] = 0.f;

    const size_t offB = (size_t)b * NOFF * Pn;
    const float* upB  = g_up_cl + (size_t)b*Pn*CSn;
    const float* upg8 = upB + q*8;

    int p = p0 + vv;
    int dg = p >> 10, hg = (p >> 5) & 31, wg = p & 31;

    auto loadoffs = [&](int kk, float& z, float& y, float& x) {
        int g = kk / K3n, k = kk % K3n;
        int kz = k/9 - 1, ky = (k/3)%3 - 1, kx = k%3 - 1;
        size_t ob = offB + (size_t)(g*K3n + k)*3*Pn + p;
        z = dg + kz + g_off[ob];
        y = hg + ky + g_off[ob + Pn];
        x = wg + kx + g_off[ob + 2*Pn];
    };

    auto wpre = [&](int kk, uint4& r0, uint4& r1, uint4& r2) {
        const uint4* srcW = (const uint4*)(g_wsplit + (size_t)kk*WTILE);
        r0 = srcW[t];
        r1 = srcW[t + 256];
        if (t < 128) r2 = srcW[t + 512];
    };
    auto wst = [&](int buf, uint4 r0, uint4 r1, uint4 r2) {
        uint4* dstW = (uint4*)(sW + buf*WTILE);
        dstW[t] = r0;
        dstW[t + 256] = r1;
        if (t < 128) dstW[t + 512] = r2;
    };

    auto gather = [&](int kk, float z, float y, float x, int buf) {
        int g = kk / K3n;
        const float* upg = upg8 + g*CGn;

        float z0f = floorf(z), y0f = floorf(y), x0f = floorf(x);
        float fz = z - z0f, fy = y - y0f, fx = x - x0f;
        int z0 = (int)z0f, y0 = (int)y0f, x0 = (int)x0f;

        float wz0 = (z0   >= 0 && z0   < DDn) ? 1.f - fz : 0.f;
        float wz1 = (z0+1 >= 0 && z0+1 < DDn) ? fz       : 0.f;
        float wy0 = (y0   >= 0 && y0   < DHn) ? 1.f - fy : 0.f;
        float wy1 = (y0+1 >= 0 && y0+1 < DHn) ? fy       : 0.f;
        float wx0 = (x0   >= 0 && x0   < DWn) ? 1.f - fx : 0.f;
        float wx1 = (x0+1 >= 0 && x0+1 < DWn) ? fx       : 0.f;
        int zi0 = min(max(z0,   0), DDn-1) << 10;
        int zi1 = min(max(z0+1, 0), DDn-1) << 10;
        int yi0 = min(max(y0,   0), DHn-1) << 5;
        int yi1 = min(max(y0+1, 0), DHn-1) << 5;
        int xi0 = min(max(x0,   0), DWn-1);
        int xi1 = min(max(x0+1, 0), DWn-1);
        float w00 = wz0*wy0, w01 = wz0*wy1, w10 = wz1*wy0, w11 = wz1*wy1;
        int   i00 = zi0+yi0, i01 = zi0+yi1, i10 = zi1+yi0, i11 = zi1+yi1;

        ull s01 = 0ull, s23 = 0ull, s45 = 0ull, s67 = 0ull;
        #pragma unroll
        for (int cnr = 0; cnr < 8; ++cnr) {
            float wzy = (cnr>>2) ? ((cnr>>1)&1 ? w11 : w10) : ((cnr>>1)&1 ? w01 : w00);
            int   izy = (cnr>>2) ? ((cnr>>1)&1 ? i11 : i10) : ((cnr>>1)&1 ? i01 : i00);
            float wt  = wzy * ((cnr&1) ? wx1 : wx0);
            int   ci  = izy + ((cnr&1) ? xi1 : xi0);
            const ulonglong2* vp = (const ulonglong2*)(upg + (size_t)ci*CSn);
            ulonglong2 va = vp[0], vb = vp[1];
            ull wd = dup2(wt);
            s01 = ffma2(va.x, wd, s01); s23 = ffma2(va.y, wd, s23);
            s45 = ffma2(vb.x, wd, s45); s67 = ffma2(vb.y, wd, s67);
        }

        // bf16 split (packed cvt)
        uint32_t h01 = cvtbf2(hi32(s01), lo32(s01));
        uint32_t h23 = cvtbf2(hi32(s23), lo32(s23));
        uint32_t h45 = cvtbf2(hi32(s45), lo32(s45));
        uint32_t h67 = cvtbf2(hi32(s67), lo32(s67));
        uint32_t l01 = cvtbf2(hi32(s01) - __uint_as_float(h01 & 0xffff0000u),
                              lo32(s01) - __uint_as_float(h01 << 16));
        uint32_t l23 = cvtbf2(hi32(s23) - __uint_as_float(h23 & 0xffff0000u),
                              lo32(s23) - __uint_as_float(h23 << 16));
        uint32_t l45 = cvtbf2(hi32(s45) - __uint_as_float(h45 & 0xffff0000u),
                              lo32(s45) - __uint_as_float(h45 << 16));
        uint32_t l67 = cvtbf2(hi32(s67) - __uint_as_float(h67 & 0xffff0000u),
                              lo32(s67) - __uint_as_float(h67 << 16));
        uint8_t* rowp = sS + buf*STILE + vv*WROW + q*16;
        *(uint4*)rowp        = make_uint4(h01, h23, h45, h67);
        *(uint4*)(rowp + 32) = make_uint4(l01, l23, l45, l67);
    };

    auto domma = [&](int buf) {
        uint32_t sWb = (uint32_t)__cvta_generic_to_shared(sW + buf*WTILE);
        uint32_t sSb = (uint32_t)__cvta_generic_to_shared(sS + buf*STILE);
        uint32_t aaddr = sWb + (w*16 + (l & 15))*WROW + (l >> 4)*16;
        uint32_t ah[4], al[4];
        ldsm4(ah, aaddr);
        ldsm4(al, aaddr + 32);
        uint32_t brow = 8*(l >> 4) + (l & 7);
        uint32_t bcol = ((l >> 3) & 1)*16;
        #pragma unroll
        for (int nc = 0; nc < 4; ++nc) {
            uint32_t baddr = sSb + (nc*16 + brow)*WROW + bcol;
            uint32_t bh[4], bl[4];
            ldsm4(bh, baddr);
            ldsm4(bl, baddr + 32);
            mma16816(dacc[2*nc  ], ah, bh[0], bh[1]);
            mma16816(dacc[2*nc  ], ah, bl[0], bl[1]);
            mma16816(dacc[2*nc  ], al, bh[0], bh[1]);
            mma16816(dacc[2*nc+1], ah, bh[2], bh[3]);
            mma16816(dacc[2*nc+1], ah, bl[2], bl[3]);
            mma16816(dacc[2*nc+1], al, bh[2], bh[3]);
        }
    };

    // ---- prologue: taps 0 and 1 (each thread-half gathers its tap) ----
    {
        float z, y, x;
        loadoffs(tapsel, z, y, x);
        uint4 r0, r1, r2;
        wpre(0, r0, r1, r2); wst(0, r0, r1, r2);
        wpre(1, r0, r1, r2); wst(1, r0, r1, r2);
        gather(tapsel, z, y, x, tapsel);
    }
    __syncthreads();

    // ---- main loop: 2 taps per barrier, 1 gather per thread ----
    for (int kk = 0; kk < NTAP; kk += 2) {
        bool more = (kk + 2 < NTAP);
        int kt = kk + 2 + tapsel;
        float z, y, x;
        uint4 r0, r1, r2;
        if (more) {
            loadoffs(kt, z, y, x);
            wpre(kk + 2, r0, r1, r2);
        }

        domma(kk & 3);

        if (more) {
            wst((kk + 2) & 3, r0, r1, r2);
            wpre(kk + 3, r0, r1, r2);
        }

        domma((kk + 1) & 3);

        if (more) {
            wst((kk + 3) & 3, r0, r1, r2);
            gather(kt, z, y, x, kt & 3);
        }
        __syncthreads();
    }

    // ---- epilogue: ReLU + STG.64 ----
    int g = l >> 2, tq = l & 3;
    size_t base0 = ((size_t)b*CDn + w*16 + g)*Pn + p0 + 2*tq;
    size_t base1 = base0 + (size_t)8*Pn;
    #pragma unroll
    for (int n = 0; n < 8; ++n) {
        float2 v0 = make_float2(fmaxf(dacc[n][0], 0.f), fmaxf(dacc[n][1], 0.f));
        float2 v1 = make_float2(fmaxf(dacc[n][2], 0.f), fmaxf(dacc[n][3], 0.f));
        *(float2*)&out[base0 + n*8] = v0;
        *(float2*)&out[base1 + n*8] = v1;
    }
}

extern "C" void kernel_launch(void* const* d_in, const int* in_sizes, int n_in,
                              void* d_out, int out_size) {
    const float* src  = (const float*)d_in[0];   // feat_1x_src [2,128,8,16,16]
    const float* dst  = (const float*)d_in[1];   // feat_2x_dst [2,128,16,32,32]
    const float* woff = (const float*)d_in[2];   // w_offset [648,256]
    const float* wdcn = (const float*)d_in[3];   // w_dcn [128,128,3,3,3]
    float* out = (float*)d_out;

    cudaFuncSetAttribute(k_dcn, cudaFuncAttributeMaxDynamicSharedMemorySize,
                         DCN_SMEM);

    const int NPREP = Bn*SDn*SHn*SWn*CSn + NTAP*128*CGn + MTILES*128*256;
    k_prep     <<<(NPREP + 255)/256, 256>>>(src, woff, wdcn);
    k_upsample <<<Bn*Pn, 128>>>();
    k_cat      <<<Bn*(Pn/32), 256>>>(dst);
    k_offmma   <<<Bn*MTILES*128, 256>>>();
    k_dcn      <<<Bn*(Pn/64), 256, DCN_SMEM>>>(out);
}

// round 12
// speedup vs baseline: 1.2283x; 1.2283x over previous
#include <cuda_runtime.h>
#include <cuda_bf16.h>
#include <cstdint>

#define Bn 2
#define CSn 128
#define CDn 128
#define SDn 8
#define SHn 16
#define SWn 16
#define DDn 16
#define DHn 32
#define DWn 32
#define Pn  (DDn*DHn*DWn)      /* 16384 */
#define Gn 8
#define K3n 27
#define CGn 16                 /* CS/G */
#define NOFF (K3n*3*Gn)        /* 648 */
#define NTAP (Gn*K3n)          /* 216 */
#define WROW 80                /* padded row bytes of A/B smem tiles */
#define WTILE (128*WROW)       /* 10240 B per weight tile */
#define STILE (64*WROW)        /* 5120 B per sample tile */
#define MTILES 6               /* ceil(648/128) m-tiles for offset GEMM */
#define DCN_SMEM (4*WTILE + 4*STILE)   /* 61440 B */

typedef unsigned long long ull;

// ---------------- bf16 helpers ------------------------------------------------
__device__ __forceinline__ uint32_t cvtbf2(float hi, float lo) { // {hi,lo} packed
    uint32_t r;
    asm("cvt.rn.bf16x2.f32 %0, %1, %2;" : "=r"(r) : "f"(hi), "f"(lo));
    return r;
}
__device__ __forceinline__ uint32_t packbf(__nv_bfloat16 a, __nv_bfloat16 b) {
    __nv_bfloat162 t = __halves2bfloat162(a, b);
    return *(uint32_t*)&t;
}

// ---------------- tensor-core helpers ---------------------------------------
__device__ __forceinline__ void ldsm4(uint32_t* r, uint32_t addr) {
    asm volatile("ldmatrix.sync.aligned.m8n8.x4.shared.b16 {%0,%1,%2,%3},[%4];"
        : "=r"(r[0]), "=r"(r[1]), "=r"(r[2]), "=r"(r[3]) : "r"(addr));
}
__device__ __forceinline__ void mma16816(float* d, const uint32_t* a,
                                         uint32_t b0, uint32_t b1) {
    asm volatile(
        "mma.sync.aligned.m16n8k16.row.col.f32.bf16.bf16.f32 "
        "{%0,%1,%2,%3},{%4,%5,%6,%7},{%8,%9},{%0,%1,%2,%3};"
        : "+f"(d[0]), "+f"(d[1]), "+f"(d[2]), "+f"(d[3])
        : "r"(a[0]), "r"(a[1]), "r"(a[2]), "r"(a[3]), "r"(b0), "r"(b1));
}

// -------- device scratch ----------------------------------------------------
__device__ float g_src_cl[Bn*SDn*SHn*SWn*CSn];   // [b][z][y][x][c]
__device__ float g_up_cl[Bn*Pn*CSn];             // [b][p][c]
__device__ float g_off[Bn*NOFF*Pn];              // [b][o][p]
__device__ __align__(16) uint8_t g_wsplit[(size_t)NTAP*WTILE];       // dcn W hi/lo
__device__ __align__(16) uint8_t g_wosplit[(size_t)MTILES*16*WTILE]; // offset W hi/lo
__device__ __align__(16) __nv_bfloat16 g_cath[(size_t)Bn*Pn*256];    // cat hi [b][p][c]
__device__ __align__(16) __nv_bfloat16 g_catl[(size_t)Bn*Pn*256];    // cat lo

// -------- prep: transposes + bf16 weight splits ------------------------------
__global__ void k_prep(const float* __restrict__ src,
                       const float* __restrict__ woff,
                       const float* __restrict__ wdcn) {
    int i = blockIdx.x * blockDim.x + threadIdx.x;
    const int N1 = Bn*SDn*SHn*SWn*CSn;    // 524288
    const int N3 = NTAP*128*CGn;          // 442368
    const int N4 = MTILES*128*256;        // 196608 (768 o x 256 c)
    if (i < N1) {
        int c = i % CSn;
        int s = (i / CSn) % (SDn*SHn*SWn);
        int b = i / (CSn*SDn*SHn*SWn);
        g_src_cl[i] = src[(b*CSn + c)*(SDn*SHn*SWn) + s];
    } else if (i < N1 + N3) {
        int j = i - N1;
        int cg = j % CGn;
        int o  = (j / CGn) % 128;
        int kk = j / (CGn*128);
        int g = kk / K3n, k = kk % K3n;
        float wv = wdcn[((o*CSn) + g*CGn + cg)*K3n + k];
        __nv_bfloat16 hb = __float2bfloat16(wv);
        __nv_bfloat16 lb = __float2bfloat16(wv - __bfloat162float(hb));
        uint8_t* row = g_wsplit + (size_t)kk*WTILE + o*WROW;
        *(__nv_bfloat16*)(row + cg*2)      = hb;
        *(__nv_bfloat16*)(row + 32 + cg*2) = lb;
    } else if (i < N1 + N3 + N4) {
        int j = i - N1 - N3;
        int c = j % 256;
        int o = j / 256;                  // 0..767 (padded)
        float wv = (o < NOFF) ? woff[o*256 + c] : 0.f;
        __nv_bfloat16 hb = __float2bfloat16(wv);
        __nv_bfloat16 lb = __float2bfloat16(wv - __bfloat162float(hb));
        int mt = o >> 7, kc = c >> 4;
        uint8_t* row = g_wosplit + (size_t)(mt*16 + kc)*WTILE + (o & 127)*WROW;
        *(__nv_bfloat16*)(row + (c & 15)*2)      = hb;
        *(__nv_bfloat16*)(row + 32 + (c & 15)*2) = lb;
    }
}

// -------- trilinear 2x upsample ----------------------------------------------
__global__ void k_upsample() {
    int bp = blockIdx.x;                 // Bn*Pn blocks
    int b = bp / Pn;
    int p = bp % Pn;
    int d = p >> 10, h = (p >> 5) & 31, w = p & 31;

    float zc = d*0.5f - 0.25f, yc = h*0.5f - 0.25f, xc = w*0.5f - 0.25f;
    int zf = (int)floorf(zc), yf = (int)floorf(yc), xf = (int)floorf(xc);
    float fz = zc - zf, fy = yc - yf, fx = xc - xf;
    int z0 = min(max(zf,     0), SDn-1), z1 = min(max(zf + 1, 0), SDn-1);
    int y0 = min(max(yf,     0), SHn-1), y1 = min(max(yf + 1, 0), SHn-1);
    int x0 = min(max(xf,     0), SWn-1), x1 = min(max(xf + 1, 0), SWn-1);

    const float* base = g_src_cl + (size_t)b * (SDn*SHn*SWn) * CSn;
    int c = threadIdx.x;  // 128

    float v000 = base[(z0*256 + y0*16 + x0)*CSn + c];
    float v001 = base[(z0*256 + y0*16 + x1)*CSn + c];
    float v010 = base[(z0*256 + y1*16 + x0)*CSn + c];
    float v011 = base[(z0*256 + y1*16 + x1)*CSn + c];
    float v100 = base[(z1*256 + y0*16 + x0)*CSn + c];
    float v101 = base[(z1*256 + y0*16 + x1)*CSn + c];
    float v110 = base[(z1*256 + y1*16 + x0)*CSn + c];
    float v111 = base[(z1*256 + y1*16 + x1)*CSn + c];

    float r0 = (1.f-fy)*((1.f-fx)*v000 + fx*v001) + fy*((1.f-fx)*v010 + fx*v011);
    float r1 = (1.f-fy)*((1.f-fx)*v100 + fx*v101) + fy*((1.f-fx)*v110 + fx*v111);
    g_up_cl[((size_t)b*Pn + p)*CSn + c] = (1.f-fz)*r0 + fz*r1;
}

// -------- build pre-split bf16 cat image [b][p][256c] ------------------------
__global__ void __launch_bounds__(256) k_cat(const float* __restrict__ dst) {
    __shared__ float cat_s[256*33];
    int blk = blockIdx.x;               // Bn*(Pn/32)
    int b  = blk / (Pn/32);
    int p0 = (blk % (Pn/32)) * 32;
    int t = threadIdx.x;

    for (int i = t; i < 128*32; i += 256) {
        int c = i >> 5, v = i & 31;
        cat_s[c*33 + v] = dst[((size_t)b*CDn + c)*Pn + p0 + v];
    }
    for (int i = t; i < 32*128; i += 256) {
        int v = i >> 7, c = i & 127;
        cat_s[(128 + c)*33 + v] = 2.0f * g_up_cl[((size_t)b*Pn + p0 + v)*CSn + c];
    }
    __syncthreads();

    int v = t & 31, cg = t >> 5;        // 8 groups of 32 channels
    uint32_t oh[16], ol[16];
    #pragma unroll
    for (int j = 0; j < 16; ++j) {
        float f0 = cat_s[(cg*32 + 2*j    )*33 + v];
        float f1 = cat_s[(cg*32 + 2*j + 1)*33 + v];
        uint32_t h = cvtbf2(f1, f0);
        float h0f = __uint_as_float(h << 16);
        float h1f = __uint_as_float(h & 0xffff0000u);
        oh[j] = h;
        ol[j] = cvtbf2(f1 - h1f, f0 - h0f);
    }
    size_t base = ((size_t)b*Pn + p0 + v)*256 + cg*32;
    uint4* dh = (uint4*)&g_cath[base];
    uint4* dl = (uint4*)&g_catl[base];
    #pragma unroll
    for (int j = 0; j < 4; ++j) {
        dh[j] = make_uint4(oh[4*j], oh[4*j+1], oh[4*j+2], oh[4*j+3]);
        dl[j] = make_uint4(ol[4*j], ol[4*j+1], ol[4*j+2], ol[4*j+3]);
    }
}

// -------- offset GEMM on tensor cores, dual N-tile (R11 version, kept) -------
__global__ void __launch_bounds__(256) k_offmma() {
    __shared__ __align__(16) uint8_t sW[2][WTILE];      // 20KB
    __shared__ __align__(16) uint8_t sS[2][2][STILE];   // 20KB

    int blk = blockIdx.x;               // Bn*MTILES*128 = 1536
    int b  = blk / (MTILES*128);
    int r  = blk % (MTILES*128);
    int mt = r / 128;
    int p0 = (r % 128) * 128;
    int t  = threadIdx.x;
    int w  = t >> 5, l = t & 31;

    float dacc[2][8][4];
    #pragma unroll
    for (int tl = 0; tl < 2; ++tl)
        #pragma unroll
        for (int n = 0; n < 8; ++n)
            #pragma unroll
            for (int j = 0; j < 4; ++j) dacc[tl][n][j] = 0.f;

    int btile = t >> 7, brow = (t & 127) >> 1, bpart = t & 1;
    const __nv_bfloat16* catsrc = (bpart ? g_catl : g_cath)
                                + ((size_t)b*Pn + p0 + btile*64 + brow)*256;

    auto domma = [&](int buf) {
        uint32_t sWb = (uint32_t)__cvta_generic_to_shared(&sW[buf][0]);
        uint32_t aaddr = sWb + (w*16 + (l & 15))*WROW + (l >> 4)*16;
        uint32_t ah[4], al[4];
        ldsm4(ah, aaddr);
        ldsm4(al, aaddr + 32);
        uint32_t br = 8*(l >> 4) + (l & 7);
        uint32_t bc = ((l >> 3) & 1)*16;
        #pragma unroll
        for (int tl = 0; tl < 2; ++tl) {
            uint32_t sSb = (uint32_t)__cvta_generic_to_shared(&sS[buf][tl][0]);
            #pragma unroll
            for (int nc = 0; nc < 4; ++nc) {
                uint32_t baddr = sSb + (nc*16 + br)*WROW + bc;
                uint32_t bh[4], bl[4];
                ldsm4(bh, baddr);
                ldsm4(bl, baddr + 32);
                mma16816(dacc[tl][2*nc  ], ah, bh[0], bh[1]);
                mma16816(dacc[tl][2*nc  ], ah, bl[0], bl[1]);
                mma16816(dacc[tl][2*nc  ], al, bh[0], bh[1]);
                mma16816(dacc[tl][2*nc+1], ah, bh[2], bh[3]);
                mma16816(dacc[tl][2*nc+1], ah, bl[2], bl[3]);
                mma16816(dacc[tl][2*nc+1], al, bh[2], bh[3]);
            }
        }
    };

    // prologue: chunk 0
    {
        const uint4* srcW = (const uint4*)(g_wosplit + (size_t)(mt*16)*WTILE);
        uint4* dW = (uint4*)sW[0];
        dW[t] = srcW[t];
        dW[t + 256] = srcW[t + 256];
        if (t < 128) dW[t + 512] = srcW[t + 512];
        const uint4* s = (const uint4*)catsrc;
        uint4* dr = (uint4*)(sS[0][btile] + brow*WROW + bpart*32);
        dr[0] = s[0]; dr[1] = s[1];
    }
    __syncthreads();

    for (int kc = 0; kc < 16; ++kc) {
        int cur = kc & 1;
        bool more = (kc + 1 < 16);
        uint4 wa, wb, wc2, b0, b1;
        if (more) {
            const uint4* srcW = (const uint4*)(g_wosplit + (size_t)(mt*16 + kc + 1)*WTILE);
            wa = srcW[t];
            wb = srcW[t + 256];
            if (t < 128) wc2 = srcW[t + 512];
            const uint4* s = (const uint4*)(catsrc + (kc + 1)*16);
            b0 = s[0]; b1 = s[1];
        }
        domma(cur);
        if (more) {
            int nb = cur ^ 1;
            uint4* dW = (uint4*)sW[nb];
            dW[t] = wa;
            dW[t + 256] = wb;
            if (t < 128) dW[t + 512] = wc2;
            uint4* dr = (uint4*)(sS[nb][btile] + brow*WROW + bpart*32);
            dr[0] = b0; dr[1] = b1;
        }
        __syncthreads();
    }

    // epilogue: write g_off (fp32, guarded o<648), both sub-tiles
    int g = l >> 2, tq = l & 3;
    int o0 = mt*128 + w*16 + g;
    int o1 = o0 + 8;
    #pragma unroll
    for (int tl = 0; tl < 2; ++tl) {
        size_t base0 = ((size_t)b*NOFF + o0)*Pn + p0 + tl*64 + 2*tq;
        size_t base1 = ((size_t)b*NOFF + o1)*Pn + p0 + tl*64 + 2*tq;
        #pragma unroll
        for (int n = 0; n < 8; ++n) {
            if (o0 < NOFF)
                *(float2*)&g_off[base0 + n*8] = make_float2(dacc[tl][n][0], dacc[tl][n][1]);
            if (o1 < NOFF)
                *(float2*)&g_off[base1 + n*8] = make_float2(dacc[tl][n][2], dacc[tl][n][3]);
        }
    }
}

// -------- fused deformable sampling + bf16-split tensor GEMM + ReLU ---------
// (R10 version — byte-identical revert)
// block: 64 voxels, 256 threads, 2 CTAs/SM; 4-buffer ring, 2 taps per barrier.
__global__ void __launch_bounds__(256, 2) k_dcn(float* __restrict__ out) {
    extern __shared__ __align__(16) uint8_t dyn[];
    uint8_t* sW = dyn;                  // 4 x WTILE
    uint8_t* sS = dyn + 4*WTILE;        // 4 x STILE

    int blk = blockIdx.x;               // Bn*(Pn/64) = 512
    int b  = blk >> 8;
    int p0 = (blk & 255) * 64;
    int t  = threadIdx.x;
    int w  = t >> 5, l = t & 31;
    int vv = t >> 2, q = t & 3;

    float dacc[8][4];
    #pragma unroll
    for (int n = 0; n < 8; ++n)
        #pragma unroll
        for (int j = 0; j < 4; ++j) dacc[n][j] = 0.f;

    const size_t offB = (size_t)b * NOFF * Pn;
    const float* upB  = g_up_cl + (size_t)b*Pn*CSn;
    const float* upg4 = upB + q*4;

    int p = p0 + vv;
    int dg = p >> 10, hg = (p >> 5) & 31, wg = p & 31;

    auto loadoffs = [&](int kk, float& z, float& y, float& x) {
        int g = kk / K3n, k = kk % K3n;
        int kz = k/9 - 1, ky = (k/3)%3 - 1, kx = k%3 - 1;
        size_t ob = offB + (size_t)(g*K3n + k)*3*Pn + p;
        z = dg + kz + g_off[ob];
        y = hg + ky + g_off[ob + Pn];
        x = wg + kx + g_off[ob + 2*Pn];
    };

    auto wpre = [&](int kk, uint4& r0, uint4& r1, uint4& r2) {
        const uint4* srcW = (const uint4*)(g_wsplit + (size_t)kk*WTILE);
        r0 = srcW[t];
        r1 = srcW[t + 256];
        if (t < 128) r2 = srcW[t + 512];
    };
    auto wst = [&](int buf, uint4 r0, uint4 r1, uint4 r2) {
        uint4* dstW = (uint4*)(sW + buf*WTILE);
        dstW[t] = r0;
        dstW[t + 256] = r1;
        if (t < 128) dstW[t + 512] = r2;
    };

    auto gather = [&](int kk, float z, float y, float x, int buf) {
        int g = kk / K3n;
        const float* upg = upg4 + g*CGn;

        float z0f = floorf(z), y0f = floorf(y), x0f = floorf(x);
        float fz = z - z0f, fy = y - y0f, fx = x - x0f;
        int z0 = (int)z0f, y0 = (int)y0f, x0 = (int)x0f;

        float wz0 = (z0   >= 0 && z0   < DDn) ? 1.f - fz : 0.f;
        float wz1 = (z0+1 >= 0 && z0+1 < DDn) ? fz       : 0.f;
        float wy0 = (y0   >= 0 && y0   < DHn) ? 1.f - fy : 0.f;
        float wy1 = (y0+1 >= 0 && y0+1 < DHn) ? fy       : 0.f;
        float wx0 = (x0   >= 0 && x0   < DWn) ? 1.f - fx : 0.f;
        float wx1 = (x0+1 >= 0 && x0+1 < DWn) ? fx       : 0.f;
        int zi0 = min(max(z0,   0), DDn-1) << 10;
        int zi1 = min(max(z0+1, 0), DDn-1) << 10;
        int yi0 = min(max(y0,   0), DHn-1) << 5;
        int yi1 = min(max(y0+1, 0), DHn-1) << 5;
        int xi0 = min(max(x0,   0), DWn-1);
        int xi1 = min(max(x0+1, 0), DWn-1);
        float w00 = wz0*wy0, w01 = wz0*wy1, w10 = wz1*wy0, w11 = wz1*wy1;
        int   i00 = zi0+yi0, i01 = zi0+yi1, i10 = zi1+yi0, i11 = zi1+yi1;

        float4 sa = make_float4(0.f, 0.f, 0.f, 0.f);
        #pragma unroll
        for (int cnr = 0; cnr < 8; ++cnr) {
            float wzy = (cnr>>2) ? ((cnr>>1)&1 ? w11 : w10) : ((cnr>>1)&1 ? w01 : w00);
            int   izy = (cnr>>2) ? ((cnr>>1)&1 ? i11 : i10) : ((cnr>>1)&1 ? i01 : i00);
            float wt  = wzy * ((cnr&1) ? wx1 : wx0);
            int   ci  = izy + ((cnr&1) ? xi1 : xi0);
            float4 v = *(const float4*)(upg + (size_t)ci*CSn);
            sa.x += wt*v.x; sa.y += wt*v.y; sa.z += wt*v.z; sa.w += wt*v.w;
        }
        uint32_t h01 = cvtbf2(sa.y, sa.x);
        uint32_t h23 = cvtbf2(sa.w, sa.z);
        uint32_t l01 = cvtbf2(sa.y - __uint_as_float(h01 & 0xffff0000u),
                              sa.x - __uint_as_float(h01 << 16));
        uint32_t l23 = cvtbf2(sa.w - __uint_as_float(h23 & 0xffff0000u),
                              sa.z - __uint_as_float(h23 << 16));
        uint8_t* rowp = sS + buf*STILE + vv*WROW + q*8;
        *(uint2*)rowp        = make_uint2(h01, h23);
        *(uint2*)(rowp + 32) = make_uint2(l01, l23);
    };

    auto domma = [&](int buf) {
        uint32_t sWb = (uint32_t)__cvta_generic_to_shared(sW + buf*WTILE);
        uint32_t sSb = (uint32_t)__cvta_generic_to_shared(sS + buf*STILE);
        uint32_t aaddr = sWb + (w*16 + (l & 15))*WROW + (l >> 4)*16;
        uint32_t ah[4], al[4];
        ldsm4(ah, aaddr);
        ldsm4(al, aaddr + 32);
        uint32_t brow = 8*(l >> 4) + (l & 7);
        uint32_t bcol = ((l >> 3) & 1)*16;
        #pragma unroll
        for (int nc = 0; nc < 4; ++nc) {
            uint32_t baddr = sSb + (nc*16 + brow)*WROW + bcol;
            uint32_t bh[4], bl[4];
            ldsm4(bh, baddr);
            ldsm4(bl, baddr + 32);
            mma16816(dacc[2*nc  ], ah, bh[0], bh[1]);
            mma16816(dacc[2*nc  ], ah, bl[0], bl[1]);
            mma16816(dacc[2*nc  ], al, bh[0], bh[1]);
            mma16816(dacc[2*nc+1], ah, bh[2], bh[3]);
            mma16816(dacc[2*nc+1], ah, bl[2], bl[3]);
            mma16816(dacc[2*nc+1], al, bh[2], bh[3]);
        }
    };

    // ---- prologue: taps 0 and 1 ----
    {
        float z0, y0, x0, z1, y1, x1;
        loadoffs(0, z0, y0, x0);
        loadoffs(1, z1, y1, x1);
        uint4 r0, r1, r2;
        wpre(0, r0, r1, r2); wst(0, r0, r1, r2);
        wpre(1, r0, r1, r2); wst(1, r0, r1, r2);
        gather(0, z0, y0, x0, 0);
        gather(1, z1, y1, x1, 1);
    }
    __syncthreads();

    // ---- main loop: 2 taps per barrier ----
    for (int kk = 0; kk < NTAP; kk += 2) {
        bool more = (kk + 2 < NTAP);
        float z2, y2, x2, z3, y3, x3;
        uint4 r0, r1, r2;
        if (more) {
            loadoffs(kk + 2, z2, y2, x2);
            loadoffs(kk + 3, z3, y3, x3);
            wpre(kk + 2, r0, r1, r2);
        }

        domma(kk & 3);

        if (more) {
            wst((kk + 2) & 3, r0, r1, r2);
            wpre(kk + 3, r0, r1, r2);
        }

        domma((kk + 1) & 3);

        if (more) {
            wst((kk + 3) & 3, r0, r1, r2);
            gather(kk + 2, z2, y2, x2, (kk + 2) & 3);
            gather(kk + 3, z3, y3, x3, (kk + 3) & 3);
        }
        __syncthreads();
    }

    // ---- epilogue: ReLU + STG.64 ----
    int g = l >> 2, tq = l & 3;
    size_t base0 = ((size_t)b*CDn + w*16 + g)*Pn + p0 + 2*tq;
    size_t base1 = base0 + (size_t)8*Pn;
    #pragma unroll
    for (int n = 0; n < 8; ++n) {
        float2 v0 = make_float2(fmaxf(dacc[n][0], 0.f), fmaxf(dacc[n][1], 0.f));
        float2 v1 = make_float2(fmaxf(dacc[n][2], 0.f), fmaxf(dacc[n][3], 0.f));
        *(float2*)&out[base0 + n*8] = v0;
        *(float2*)&out[base1 + n*8] = v1;
    }
}

extern "C" void kernel_launch(void* const* d_in, const int* in_sizes, int n_in,
                              void* d_out, int out_size) {
    const float* src  = (const float*)d_in[0];   // feat_1x_src [2,128,8,16,16]
    const float* dst  = (const float*)d_in[1];   // feat_2x_dst [2,128,16,32,32]
    const float* woff = (const float*)d_in[2];   // w_offset [648,256]
    const float* wdcn = (const float*)d_in[3];   // w_dcn [128,128,3,3,3]
    float* out = (float*)d_out;

    cudaFuncSetAttribute(k_dcn, cudaFuncAttributeMaxDynamicSharedMemorySize,
                         DCN_SMEM);

    const int NPREP = Bn*SDn*SHn*SWn*CSn + NTAP*128*CGn + MTILES*128*256;
    k_prep     <<<(NPREP + 255)/256, 256>>>(src, woff, wdcn);
    k_upsample <<<Bn*Pn, 128>>>();
    k_cat      <<<Bn*(Pn/32), 256>>>(dst);
    k_offmma   <<<Bn*MTILES*128, 256>>>();
    k_dcn      <<<Bn*(Pn/64), 256, DCN_SMEM>>>(out);
}